// round 2
// baseline (speedup 1.0000x reference)
#include <cuda_runtime.h>
#include <cstdint>

#define B_DIM 2048
#define K_DIM 256
#define U_DIM 512

#define BM 128
#define BN 64
#define BK 16
#define NTILES (K_DIM / BK)   // 16
#define SY_STRIDE (BM + 4)    // pad (528B row, keeps 16B alignment)

// ---- packed f32x2 helpers (sm_103a) ----
__device__ __forceinline__ unsigned long long f2_fma(unsigned long long a,
                                                     unsigned long long b,
                                                     unsigned long long c) {
    unsigned long long d;
    asm("fma.rn.f32x2 %0, %1, %2, %3;" : "=l"(d) : "l"(a), "l"(b), "l"(c));
    return d;
}
__device__ __forceinline__ unsigned long long f2_mul(unsigned long long a,
                                                     unsigned long long b) {
    unsigned long long d;
    asm("mul.rn.f32x2 %0, %1, %2;" : "=l"(d) : "l"(a), "l"(b));
    return d;
}
__device__ __forceinline__ unsigned long long f2_pack(float a, float b) {
    unsigned long long d;
    asm("mov.b64 %0, {%1, %2};" : "=l"(d) : "f"(a), "f"(b));
    return d;
}
__device__ __forceinline__ float2 f2_unpack(unsigned long long v) {
    float2 r;
    asm("mov.b64 {%0, %1}, %2;" : "=f"(r.x), "=f"(r.y) : "l"(v));
    return r;
}

__global__ __launch_bounds__(256, 1)
void pew_kernel(const float* __restrict__ x,
                const float* __restrict__ w,
                float* __restrict__ out) {
    // sY holds y = 1 - x, TRANSPOSED to [k][b] so b is contiguous (f32x2 pairs).
    // sW holds wn = -w in [k][u] layout.
    __shared__ __align__(16) float sY[2][BK][SY_STRIDE];
    __shared__ __align__(16) float sW[2][BK][BN];

    const int tid = threadIdx.x;
    const int tx  = tid & 15;          // u direction (16 threads)
    const int ty  = tid >> 4;          // b direction (16 threads)
    const int ub  = blockIdx.x * BN;
    const int bb  = blockIdx.y * BM;

    // staging coordinates
    const int xb0 = tid >> 2;          // 0..63 ; second half at +64
    const int xkq = (tid & 3) * 4;     // k-quad within tile
    const int wu  = (tid & 15) * 4;    // u offset for w float4
    const int wk  = tid >> 4;          // k row for w float4

    const unsigned long long ONE2 = 0x3F8000003F800000ULL; // {1.0f, 1.0f}

    unsigned long long acc[4][4];      // [b-pair][u], packed over b
#pragma unroll
    for (int i = 0; i < 4; i++)
#pragma unroll
        for (int j = 0; j < 4; j++) acc[i][j] = ONE2;

    // ---- stage tile 0 ----
    float4 rx0 = *(const float4*)(x + (bb + xb0) * K_DIM + xkq);
    float4 rx1 = *(const float4*)(x + (bb + xb0 + 64) * K_DIM + xkq);
    float4 rw  = *(const float4*)(w + wk * U_DIM + ub + wu);

    sY[0][xkq + 0][xb0] = 1.0f - rx0.x;
    sY[0][xkq + 1][xb0] = 1.0f - rx0.y;
    sY[0][xkq + 2][xb0] = 1.0f - rx0.z;
    sY[0][xkq + 3][xb0] = 1.0f - rx0.w;
    sY[0][xkq + 0][xb0 + 64] = 1.0f - rx1.x;
    sY[0][xkq + 1][xb0 + 64] = 1.0f - rx1.y;
    sY[0][xkq + 2][xb0 + 64] = 1.0f - rx1.z;
    sY[0][xkq + 3][xb0 + 64] = 1.0f - rx1.w;
    {
        float4 nw = make_float4(-rw.x, -rw.y, -rw.z, -rw.w);
        *(float4*)&sW[0][wk][wu] = nw;
    }
    __syncthreads();

#pragma unroll 1
    for (int t = 0; t < NTILES; t++) {
        const int cur = t & 1;

        // prefetch next tile to registers (overlaps with compute)
        if (t + 1 < NTILES) {
            const int k0 = (t + 1) * BK;
            rx0 = *(const float4*)(x + (bb + xb0) * K_DIM + k0 + xkq);
            rx1 = *(const float4*)(x + (bb + xb0 + 64) * K_DIM + k0 + xkq);
            rw  = *(const float4*)(w + (k0 + wk) * U_DIM + ub + wu);
        }

        // ---- compute on buffer `cur` ----
#pragma unroll
        for (int k = 0; k < BK; k++) {
            // 8 consecutive y values (b-contiguous) as 4 ready-made f32x2 pairs
            const ulonglong2 ya = *(const ulonglong2*)&sY[cur][k][ty * 8];
            const ulonglong2 yb = *(const ulonglong2*)&sY[cur][k][ty * 8 + 4];
            const float4 wv = *(const float4*)&sW[cur][k][tx * 4];

            unsigned long long wp[4];
            wp[0] = f2_pack(wv.x, wv.x);
            wp[1] = f2_pack(wv.y, wv.y);
            wp[2] = f2_pack(wv.z, wv.z);
            wp[3] = f2_pack(wv.w, wv.w);

            const unsigned long long yv[4] = {ya.x, ya.y, yb.x, yb.y};
#pragma unroll
            for (int i = 0; i < 4; i++)
#pragma unroll
                for (int j = 0; j < 4; j++)
                    // t = (-w)*(1-x) + 1 = x*w + (1-w);  acc *= t
                    acc[i][j] = f2_mul(acc[i][j], f2_fma(wp[j], yv[i], ONE2));
        }

        // ---- store prefetched tile into the other buffer ----
        if (t + 1 < NTILES) {
            const int nb = cur ^ 1;
            sY[nb][xkq + 0][xb0] = 1.0f - rx0.x;
            sY[nb][xkq + 1][xb0] = 1.0f - rx0.y;
            sY[nb][xkq + 2][xb0] = 1.0f - rx0.z;
            sY[nb][xkq + 3][xb0] = 1.0f - rx0.w;
            sY[nb][xkq + 0][xb0 + 64] = 1.0f - rx1.x;
            sY[nb][xkq + 1][xb0 + 64] = 1.0f - rx1.y;
            sY[nb][xkq + 2][xb0 + 64] = 1.0f - rx1.z;
            sY[nb][xkq + 3][xb0 + 64] = 1.0f - rx1.w;
            float4 nw = make_float4(-rw.x, -rw.y, -rw.z, -rw.w);
            *(float4*)&sW[nb][wk][wu] = nw;
            __syncthreads();
        }
    }

    // ---- epilogue: unpack b-pairs, vectorized STG.128 ----
    const int ob = bb + ty * 8;
    const int ou = ub + tx * 4;
#pragma unroll
    for (int i2 = 0; i2 < 4; i2++) {
        const float2 c0 = f2_unpack(acc[i2][0]);
        const float2 c1 = f2_unpack(acc[i2][1]);
        const float2 c2 = f2_unpack(acc[i2][2]);
        const float2 c3 = f2_unpack(acc[i2][3]);
        float4 vlo = make_float4(c0.x, c1.x, c2.x, c3.x);
        float4 vhi = make_float4(c0.y, c1.y, c2.y, c3.y);
        *(float4*)(out + (ob + i2 * 2 + 0) * U_DIM + ou) = vlo;
        *(float4*)(out + (ob + i2 * 2 + 1) * U_DIM + ou) = vhi;
    }
}

extern "C" void kernel_launch(void* const* d_in, const int* in_sizes, int n_in,
                              void* d_out, int out_size) {
    const float* x = (const float*)d_in[0];   // [2048, 256]
    const float* w = (const float*)d_in[1];   // [256 * 512], k-major, u contiguous
    float* out = (float*)d_out;               // [2048, 512]

    dim3 grid(U_DIM / BN, B_DIM / BM);        // (8, 16) = 128 blocks
    pew_kernel<<<grid, 256>>>(x, w, out);
}